// round 4
// baseline (speedup 1.0000x reference)
#include <cuda_runtime.h>

// Problem constants
#define T_  40
#define H_  40
#define G_  160   // 4*H
#define C_  4
#define BLK 128

__device__ __forceinline__ float fsigm(float x) {
    // 1/(1+exp(-x)) via MUFU EX2 + RCP
    return __fdividef(1.0f, 1.0f + __expf(-x));
}
__device__ __forceinline__ float ftanh(float x) {
    float e = __expf(-2.0f * x);
    return __fdividef(1.0f - e, 1.0f + e);
}

extern __shared__ float smem[];

__global__ __launch_bounds__(BLK)
void lstm_fused_kernel(const float* __restrict__ x,
                       const float* __restrict__ W_ih,
                       const float* __restrict__ W_hh,
                       const float* __restrict__ b_ih,
                       const float* __restrict__ b_hh,
                       const float* __restrict__ W_fc,
                       const float* __restrict__ b_fc,
                       float* __restrict__ out,
                       long long logit_off,   // -1 = don't write logits
                       long long arg_off)     // -1 = don't write argmax
{
    // Shared layout
    float* sW   = smem;                  // [160][40] row-major  (6400)
    float* sWin = sW   + G_ * H_;        // [160]
    float* sB   = sWin + G_;             // [160] b_ih+b_hh
    float* sWfc = sB   + G_;             // [4][40]              (160)
    float* sbfc = sWfc + C_ * H_;        // [4] (padded to 8)
    float* sX   = sbfc + 8;              // [128][41] padded x tile
    float* sC   = sX   + BLK * 41;       // [40][128] cell state
    float* sHn  = sC   + H_ * BLK;       // [40][128] h_new staging

    const int tid = threadIdx.x;

    // Stage weights (broadcast-reused by all threads)
    for (int i = tid; i < G_ * H_; i += BLK) sW[i] = W_hh[i];
    for (int i = tid; i < G_; i += BLK) { sWin[i] = W_ih[i]; sB[i] = b_ih[i] + b_hh[i]; }
    for (int i = tid; i < C_ * H_; i += BLK) sWfc[i] = W_fc[i];
    if (tid < C_) sbfc[tid] = b_fc[tid];

    // Stage this block's x rows coalesced -> padded shared rows
    const long long seq = (long long)blockIdx.x * BLK + tid;
    const float* xblk = x + (long long)blockIdx.x * BLK * T_;
    for (int i = tid; i < BLK * T_; i += BLK)
        sX[(i / T_) * 41 + (i % T_)] = xblk[i];
    __syncthreads();

    // h in registers (always statically indexed)
    float h[H_];
#pragma unroll
    for (int k = 0; k < H_; k++) h[k] = 0.0f;
#pragma unroll
    for (int u = 0; u < H_; u++) sC[u * BLK + tid] = 0.0f;

    const float* xr = sX + tid * 41;

#pragma unroll 1
    for (int t = 0; t < T_; t++) {
        const float xt = xr[t];
#pragma unroll 1
        for (int u = 0; u < H_; u++) {
            // gate rows: i=u, f=40+u, g=80+u, o=120+u
            float ai = fmaf(xt, sWin[u],          sB[u]);
            float af = fmaf(xt, sWin[H_ + u],     sB[H_ + u]);
            float ag = fmaf(xt, sWin[2 * H_ + u], sB[2 * H_ + u]);
            float ao = fmaf(xt, sWin[3 * H_ + u], sB[3 * H_ + u]);
            const float* Wi = sW + (size_t)u * H_;
            const float* Wf = sW + (size_t)(H_ + u) * H_;
            const float* Wg = sW + (size_t)(2 * H_ + u) * H_;
            const float* Wo = sW + (size_t)(3 * H_ + u) * H_;
#pragma unroll
            for (int k = 0; k < H_; k += 4) {
                float4 vi = *(const float4*)(Wi + k);
                float4 vf = *(const float4*)(Wf + k);
                float4 vg = *(const float4*)(Wg + k);
                float4 vo = *(const float4*)(Wo + k);
                ai = fmaf(vi.x, h[k], ai);     af = fmaf(vf.x, h[k], af);
                ag = fmaf(vg.x, h[k], ag);     ao = fmaf(vo.x, h[k], ao);
                ai = fmaf(vi.y, h[k + 1], ai); af = fmaf(vf.y, h[k + 1], af);
                ag = fmaf(vg.y, h[k + 1], ag); ao = fmaf(vo.y, h[k + 1], ao);
                ai = fmaf(vi.z, h[k + 2], ai); af = fmaf(vf.z, h[k + 2], af);
                ag = fmaf(vg.z, h[k + 2], ag); ao = fmaf(vo.z, h[k + 2], ao);
                ai = fmaf(vi.w, h[k + 3], ai); af = fmaf(vf.w, h[k + 3], af);
                ag = fmaf(vg.w, h[k + 3], ag); ao = fmaf(vo.w, h[k + 3], ao);
            }
            const float ig = fsigm(ai);
            const float fg = fsigm(af);
            const float gg = ftanh(ag);
            const float og = fsigm(ao);
            const float cold = sC[u * BLK + tid];
            const float cn = fmaf(fg, cold, ig * gg);
            sC[u * BLK + tid] = cn;
            sHn[u * BLK + tid] = og * ftanh(cn);
        }
        // commit h_new -> h (same-thread locations, no sync needed)
#pragma unroll
        for (int k = 0; k < H_; k++) h[k] = sHn[k * BLK + tid];
    }

    // FC head: logits[c] = b_fc[c] + dot(h, W_fc[c])
    float lg[C_];
#pragma unroll
    for (int cc = 0; cc < C_; cc++) {
        float a = sbfc[cc];
#pragma unroll
        for (int k = 0; k < H_; k++)
            a = fmaf(sWfc[cc * H_ + k], h[k], a);
        lg[cc] = a;
    }
    // argmax, first-max-wins (matches jnp.argmax)
    int best = 0;
    float bv = lg[0];
#pragma unroll
    for (int cc = 1; cc < C_; cc++)
        if (lg[cc] > bv) { bv = lg[cc]; best = cc; }

    if (logit_off >= 0) {
        float4 v = make_float4(lg[0], lg[1], lg[2], lg[3]);
        *(float4*)(out + logit_off + seq * 4) = v;
    }
    if (arg_off >= 0)
        out[arg_off + seq] = (float)best;
}

extern "C" void kernel_launch(void* const* d_in, const int* in_sizes, int n_in,
                              void* d_out, int out_size)
{
    const float* x    = (const float*)d_in[0];
    const float* W_ih = (const float*)d_in[1];
    const float* W_hh = (const float*)d_in[2];
    const float* b_ih = (const float*)d_in[3];
    const float* b_hh = (const float*)d_in[4];
    const float* W_fc = (const float*)d_in[5];
    const float* b_fc = (const float*)d_in[6];
    float* out = (float*)d_out;

    const long long Btot = in_sizes[0] / T_;

    // Output layout: reference returns (logits [B,4] f32, argmax [B]).
    // Decide what to write from out_size.
    long long logit_off = 0, arg_off = 4LL * Btot;   // default: both
    if (out_size == (int)(Btot * 5)) {
        logit_off = 0; arg_off = 4LL * Btot;
    } else if (out_size == (int)(Btot * 4)) {
        logit_off = 0; arg_off = -1;
    } else if (out_size == (int)Btot) {
        logit_off = -1; arg_off = 0;
    }

    const size_t smem_bytes =
        (size_t)(G_ * H_ + G_ + G_ + C_ * H_ + 8 + BLK * 41 + 2 * H_ * BLK) * sizeof(float);
    cudaFuncSetAttribute(lstm_fused_kernel,
                         cudaFuncAttributeMaxDynamicSharedMemorySize,
                         (int)smem_bytes);

    const int grid = (int)((Btot + BLK - 1) / BLK);
    lstm_fused_kernel<<<grid, BLK, smem_bytes>>>(
        x, W_ih, W_hh, b_ih, b_hh, W_fc, b_fc, out, logit_off, arg_off);
}

// round 8
// speedup vs baseline: 1.4207x; 1.4207x over previous
#include <cuda_runtime.h>

// Problem constants
#define T_  40
#define H_  40
#define G_  160   // 4*H
#define C_  4
#define BLK 128
#define SPB 256   // sequences per block (2 per thread)

typedef unsigned long long ull;

__device__ __forceinline__ float fsigm(float x) {
    return __fdividef(1.0f, 1.0f + __expf(-x));
}
__device__ __forceinline__ float ftanh(float x) {
    float e = __expf(-2.0f * x);
    return __fdividef(1.0f - e, 1.0f + e);
}

// packed f32x2 helpers (sm_103a)
__device__ __forceinline__ ull pk2(float lo, float hi) {
    ull r; asm("mov.b64 %0, {%1, %2};" : "=l"(r) : "f"(lo), "f"(hi)); return r;
}
__device__ __forceinline__ void upk2(float& lo, float& hi, ull v) {
    asm("mov.b64 {%0, %1}, %2;" : "=f"(lo), "=f"(hi) : "l"(v));
}
__device__ __forceinline__ void ffma2(ull& d, ull a, ull b) {
    asm("fma.rn.f32x2 %0, %1, %2, %0;" : "+l"(d) : "l"(a), "l"(b));
}

extern __shared__ float smem[];

// Shared layout (float offsets):
//   sW    [160*40] = 6400
//   sWin  [160]           @6400
//   sB    [160]           @6560
//   sWfc  [4*40]=160      @6720
//   sbfc  [8]             @6880
//   -- 8B-aligned ull region @6888 (byte 27552) --
//   sC    ull[40*128]   (cA,cB packed per unit per thread)
//   sHA   ull[20*128]   (h pairs, seq A)
//   sHB   ull[20*128]   (h pairs, seq B)
#define OFF_WIN 6400
#define OFF_B   6560
#define OFF_WFC 6720
#define OFF_BFC 6880
#define OFF_ULL 6888
#define N_C   (H_ * BLK)       // 5120 ull
#define N_H   (20 * BLK)       // 2560 ull
#define SMEM_BYTES (OFF_ULL * 4 + (N_C + 2 * N_H) * 8)

__global__ __launch_bounds__(BLK)
void lstm_fused_kernel(const float* __restrict__ x,
                       const float* __restrict__ W_ih,
                       const float* __restrict__ W_hh,
                       const float* __restrict__ b_ih,
                       const float* __restrict__ b_hh,
                       const float* __restrict__ W_fc,
                       const float* __restrict__ b_fc,
                       float* __restrict__ out,
                       long long logit_off,
                       long long arg_off)
{
    float* sW   = smem;
    float* sWin = smem + OFF_WIN;
    float* sB   = smem + OFF_B;
    float* sWfc = smem + OFF_WFC;
    float* sbfc = smem + OFF_BFC;
    ull*   sC   = (ull*)(smem + OFF_ULL);
    ull*   sHA  = sC + N_C;
    ull*   sHB  = sHA + N_H;

    const int tid = threadIdx.x;

    // Stage weights
    for (int i = tid; i < G_ * H_; i += BLK) sW[i] = W_hh[i];
    for (int i = tid; i < G_; i += BLK) { sWin[i] = W_ih[i]; sB[i] = b_ih[i] + b_hh[i]; }
    for (int i = tid; i < C_ * H_; i += BLK) sWfc[i] = W_fc[i];
    if (tid < C_) sbfc[tid] = b_fc[tid];
    // Zero cell state
    for (int i = tid; i < N_C; i += BLK) sC[i] = 0ULL;
    __syncthreads();

    const long long seqA = (long long)blockIdx.x * SPB + tid;
    const long long seqB = seqA + BLK;
    const float* xA_ptr = x + seqA * T_;
    const float* xB_ptr = x + seqB * T_;

    // h packed as (h[2j], h[2j+1]) pairs, per sequence
    ull hA[20], hB[20];
#pragma unroll
    for (int j = 0; j < 20; j++) { hA[j] = 0ULL; hB[j] = 0ULL; }

    float xA = xA_ptr[0];
    float xB = xB_ptr[0];
    float hnAp = 0.0f, hnBp = 0.0f;

#pragma unroll 1
    for (int t = 0; t < T_; t++) {
        // prefetch next x
        float xAn = 0.0f, xBn = 0.0f;
        if (t + 1 < T_) { xAn = xA_ptr[t + 1]; xBn = xB_ptr[t + 1]; }

#pragma unroll 1
        for (int u = 0; u < H_; u++) {
            const float wi0 = sWin[u],        bi0 = sB[u];
            const float wf0 = sWin[H_ + u],   bf0 = sB[H_ + u];
            const float wg0 = sWin[2*H_ + u], bg0 = sB[2*H_ + u];
            const float wo0 = sWin[3*H_ + u], bo0 = sB[3*H_ + u];

            ull aAi = pk2(fmaf(xA, wi0, bi0), 0.0f);
            ull aAf = pk2(fmaf(xA, wf0, bf0), 0.0f);
            ull aAg = pk2(fmaf(xA, wg0, bg0), 0.0f);
            ull aAo = pk2(fmaf(xA, wo0, bo0), 0.0f);
            ull aBi = pk2(fmaf(xB, wi0, bi0), 0.0f);
            ull aBf = pk2(fmaf(xB, wf0, bf0), 0.0f);
            ull aBg = pk2(fmaf(xB, wg0, bg0), 0.0f);
            ull aBo = pk2(fmaf(xB, wo0, bo0), 0.0f);

            const ulonglong2* Wi = (const ulonglong2*)(sW + u * H_);
            const ulonglong2* Wf = (const ulonglong2*)(sW + (H_ + u) * H_);
            const ulonglong2* Wg = (const ulonglong2*)(sW + (2*H_ + u) * H_);
            const ulonglong2* Wo = (const ulonglong2*)(sW + (3*H_ + u) * H_);
#pragma unroll
            for (int c = 0; c < 10; c++) {
                ulonglong2 vi = Wi[c];
                ulonglong2 vf = Wf[c];
                ulonglong2 vg = Wg[c];
                ulonglong2 vo = Wo[c];
                ffma2(aAi, vi.x, hA[2*c]); ffma2(aAi, vi.y, hA[2*c+1]);
                ffma2(aBi, vi.x, hB[2*c]); ffma2(aBi, vi.y, hB[2*c+1]);
                ffma2(aAf, vf.x, hA[2*c]); ffma2(aAf, vf.y, hA[2*c+1]);
                ffma2(aBf, vf.x, hB[2*c]); ffma2(aBf, vf.y, hB[2*c+1]);
                ffma2(aAg, vg.x, hA[2*c]); ffma2(aAg, vg.y, hA[2*c+1]);
                ffma2(aBg, vg.x, hB[2*c]); ffma2(aBg, vg.y, hB[2*c+1]);
                ffma2(aAo, vo.x, hA[2*c]); ffma2(aAo, vo.y, hA[2*c+1]);
                ffma2(aBo, vo.x, hB[2*c]); ffma2(aBo, vo.y, hB[2*c+1]);
            }

            float lo, hi;
            upk2(lo, hi, aAi); const float vAi = lo + hi;
            upk2(lo, hi, aAf); const float vAf = lo + hi;
            upk2(lo, hi, aAg); const float vAg = lo + hi;
            upk2(lo, hi, aAo); const float vAo = lo + hi;
            upk2(lo, hi, aBi); const float vBi = lo + hi;
            upk2(lo, hi, aBf); const float vBf = lo + hi;
            upk2(lo, hi, aBg); const float vBg = lo + hi;
            upk2(lo, hi, aBo); const float vBo = lo + hi;

            const float iA = fsigm(vAi), fA = fsigm(vAf), gA = ftanh(vAg), oA = fsigm(vAo);
            const float iB = fsigm(vBi), fB = fsigm(vBf), gB = ftanh(vBg), oB = fsigm(vBo);

            float cA, cB;
            upk2(cA, cB, sC[u * BLK + tid]);
            const float cnA = fmaf(fA, cA, iA * gA);
            const float cnB = fmaf(fB, cB, iB * gB);
            sC[u * BLK + tid] = pk2(cnA, cnB);
            const float hnA = oA * ftanh(cnA);
            const float hnB = oB * ftanh(cnB);

            if (u & 1) {
                sHA[(u >> 1) * BLK + tid] = pk2(hnAp, hnA);
                sHB[(u >> 1) * BLK + tid] = pk2(hnBp, hnB);
            } else {
                hnAp = hnA; hnBp = hnB;
            }
        }

        // commit h_new -> packed h regs (same-thread slots, no sync needed)
#pragma unroll
        for (int j = 0; j < 20; j++) {
            hA[j] = sHA[j * BLK + tid];
            hB[j] = sHB[j * BLK + tid];
        }
        xA = xAn; xB = xBn;
    }

    // FC head (packed dot products)
    float lgA[C_], lgB[C_];
#pragma unroll
    for (int cc = 0; cc < C_; cc++) {
        const ulonglong2* W = (const ulonglong2*)(sWfc + cc * H_);
        ull aA = 0ULL, aB = 0ULL;
#pragma unroll
        for (int c = 0; c < 10; c++) {
            ulonglong2 w = W[c];
            ffma2(aA, w.x, hA[2*c]); ffma2(aA, w.y, hA[2*c+1]);
            ffma2(aB, w.x, hB[2*c]); ffma2(aB, w.y, hB[2*c+1]);
        }
        float lo, hi;
        upk2(lo, hi, aA); lgA[cc] = sbfc[cc] + lo + hi;
        upk2(lo, hi, aB); lgB[cc] = sbfc[cc] + lo + hi;
    }

    int bestA = 0, bestB = 0;
    float bvA = lgA[0], bvB = lgB[0];
#pragma unroll
    for (int cc = 1; cc < C_; cc++) {
        if (lgA[cc] > bvA) { bvA = lgA[cc]; bestA = cc; }
        if (lgB[cc] > bvB) { bvB = lgB[cc]; bestB = cc; }
    }

    if (logit_off >= 0) {
        *(float4*)(out + logit_off + seqA * 4) = make_float4(lgA[0], lgA[1], lgA[2], lgA[3]);
        *(float4*)(out + logit_off + seqB * 4) = make_float4(lgB[0], lgB[1], lgB[2], lgB[3]);
    }
    if (arg_off >= 0) {
        out[arg_off + seqA] = (float)bestA;
        out[arg_off + seqB] = (float)bestB;
    }
}

extern "C" void kernel_launch(void* const* d_in, const int* in_sizes, int n_in,
                              void* d_out, int out_size)
{
    const float* x    = (const float*)d_in[0];
    const float* W_ih = (const float*)d_in[1];
    const float* W_hh = (const float*)d_in[2];
    const float* b_ih = (const float*)d_in[3];
    const float* b_hh = (const float*)d_in[4];
    const float* W_fc = (const float*)d_in[5];
    const float* b_fc = (const float*)d_in[6];
    float* out = (float*)d_out;

    const long long Btot = in_sizes[0] / T_;

    long long logit_off = 0, arg_off = 4LL * Btot;   // default: both
    if (out_size == (int)(Btot * 5)) {
        logit_off = 0; arg_off = 4LL * Btot;
    } else if (out_size == (int)(Btot * 4)) {
        logit_off = 0; arg_off = -1;
    } else if (out_size == (int)Btot) {
        logit_off = -1; arg_off = 0;
    }

    cudaFuncSetAttribute(lstm_fused_kernel,
                         cudaFuncAttributeMaxDynamicSharedMemorySize,
                         (int)SMEM_BYTES);

    const int grid = (int)((Btot + SPB - 1) / SPB);
    lstm_fused_kernel<<<grid, BLK, SMEM_BYTES>>>(
        x, W_ih, W_hh, b_ih, b_hh, W_fc, b_fc, out, logit_off, arg_off);
}

// round 10
// speedup vs baseline: 1.5608x; 1.0986x over previous
#include <cuda_runtime.h>

// Problem constants
#define T_  40
#define H_  40
#define G_  160   // 4*H
#define C_  4
#define BLK 128
#define SPB 256   // sequences per block (2 per thread)

typedef unsigned long long ull;

// HW tanh (MUFU.TANH, sm_75+)
__device__ __forceinline__ float tanh_hw(float x) {
    float r; asm("tanh.approx.f32 %0, %1;" : "=f"(r) : "f"(x)); return r;
}
__device__ __forceinline__ float fsigm(float x) {
    // sigma(x) = 0.5 * (1 + tanh(x/2))
    return fmaf(0.5f, tanh_hw(0.5f * x), 0.5f);
}

// packed f32x2 helpers (sm_103a)
__device__ __forceinline__ ull pk2(float lo, float hi) {
    ull r; asm("mov.b64 %0, {%1, %2};" : "=l"(r) : "f"(lo), "f"(hi)); return r;
}
__device__ __forceinline__ void upk2(float& lo, float& hi, ull v) {
    asm("mov.b64 {%0, %1}, %2;" : "=f"(lo), "=f"(hi) : "l"(v));
}
__device__ __forceinline__ void ffma2(ull& d, ull a, ull b) {
    asm("fma.rn.f32x2 %0, %1, %2, %0;" : "+l"(d) : "l"(a), "l"(b));
}

extern __shared__ float smem[];

// Shared layout (float offsets):
//   sW    [160*40] = 6400           @0
//   sWfc  [4*40]=160                @6400
//   sbfc  [8]                       @6560
//   -- 8B-aligned ull region @6568 (byte 26272, 16B aligned) --
//   sWP  ull[160]  (w_in, 0) packed, index [u*4+gate]
//   sBP  ull[160]  (b, 0)   packed, index [u*4+gate]
//   sC   ull[40*128]
//   sHA  ull[20*128]
//   sHB  ull[20*128]
#define OFF_WFC 6400
#define OFF_BFC 6560
#define OFF_ULL 6568
#define N_C   (H_ * BLK)       // 5120 ull
#define N_H   (20 * BLK)       // 2560 ull
#define SMEM_BYTES (OFF_ULL * 4 + (2 * G_ + N_C + 2 * N_H) * 8)

__global__ __launch_bounds__(BLK)
void lstm_fused_kernel(const float* __restrict__ x,
                       const float* __restrict__ W_ih,
                       const float* __restrict__ W_hh,
                       const float* __restrict__ b_ih,
                       const float* __restrict__ b_hh,
                       const float* __restrict__ W_fc,
                       const float* __restrict__ b_fc,
                       float* __restrict__ out,
                       long long logit_off,
                       long long arg_off)
{
    float* sW   = smem;
    float* sWfc = smem + OFF_WFC;
    float* sbfc = smem + OFF_BFC;
    ull*   sWP  = (ull*)(smem + OFF_ULL);
    ull*   sBP  = sWP + G_;
    ull*   sC   = sBP + G_;
    ull*   sHA  = sC + N_C;
    ull*   sHB  = sHA + N_H;

    const int tid = threadIdx.x;

    // Stage weights
    for (int i = tid; i < G_ * H_; i += BLK) sW[i] = W_hh[i];
    for (int i = tid; i < G_; i += BLK) {
        const int g = i / H_, u = i % H_;
        sWP[u * 4 + g] = pk2(W_ih[i], 0.0f);
        sBP[u * 4 + g] = pk2(b_ih[i] + b_hh[i], 0.0f);
    }
    for (int i = tid; i < C_ * H_; i += BLK) sWfc[i] = W_fc[i];
    if (tid < C_) sbfc[tid] = b_fc[tid];
    for (int i = tid; i < N_C; i += BLK) sC[i] = 0ULL;
    __syncthreads();

    const long long seqA = (long long)blockIdx.x * SPB + tid;
    const long long seqB = seqA + BLK;
    const float* xA_ptr = x + seqA * T_;
    const float* xB_ptr = x + seqB * T_;

    ull hA[20], hB[20];
#pragma unroll
    for (int j = 0; j < 20; j++) { hA[j] = 0ULL; hB[j] = 0ULL; }

    float xA = xA_ptr[0];
    float xB = xB_ptr[0];
    float hnAp = 0.0f, hnBp = 0.0f;

#pragma unroll 1
    for (int t = 0; t < T_; t++) {
        // prefetch next x
        float xAn = 0.0f, xBn = 0.0f;
        if (t + 1 < T_) { xAn = xA_ptr[t + 1]; xBn = xB_ptr[t + 1]; }

        const ull xx2A = pk2(xA, xA);
        const ull xx2B = pk2(xB, xB);

#pragma unroll 2
        for (int u = 0; u < H_; u++) {
            // accumulator init: (x*w_in + b, 0) via packed fma
            const ulonglong2 bp01 = *(const ulonglong2*)(sBP + u * 4);
            const ulonglong2 bp23 = *(const ulonglong2*)(sBP + u * 4 + 2);
            const ulonglong2 wp01 = *(const ulonglong2*)(sWP + u * 4);
            const ulonglong2 wp23 = *(const ulonglong2*)(sWP + u * 4 + 2);

            ull aAi = bp01.x, aAf = bp01.y, aAg = bp23.x, aAo = bp23.y;
            ull aBi = bp01.x, aBf = bp01.y, aBg = bp23.x, aBo = bp23.y;
            ffma2(aAi, wp01.x, xx2A); ffma2(aAf, wp01.y, xx2A);
            ffma2(aAg, wp23.x, xx2A); ffma2(aAo, wp23.y, xx2A);
            ffma2(aBi, wp01.x, xx2B); ffma2(aBf, wp01.y, xx2B);
            ffma2(aBg, wp23.x, xx2B); ffma2(aBo, wp23.y, xx2B);

            const ulonglong2* Wi = (const ulonglong2*)(sW + u * H_);
            const ulonglong2* Wf = (const ulonglong2*)(sW + (H_ + u) * H_);
            const ulonglong2* Wg = (const ulonglong2*)(sW + (2*H_ + u) * H_);
            const ulonglong2* Wo = (const ulonglong2*)(sW + (3*H_ + u) * H_);
#pragma unroll
            for (int c = 0; c < 10; c++) {
                ulonglong2 vi = Wi[c];
                ulonglong2 vf = Wf[c];
                ulonglong2 vg = Wg[c];
                ulonglong2 vo = Wo[c];
                ffma2(aAi, vi.x, hA[2*c]); ffma2(aAi, vi.y, hA[2*c+1]);
                ffma2(aBi, vi.x, hB[2*c]); ffma2(aBi, vi.y, hB[2*c+1]);
                ffma2(aAf, vf.x, hA[2*c]); ffma2(aAf, vf.y, hA[2*c+1]);
                ffma2(aBf, vf.x, hB[2*c]); ffma2(aBf, vf.y, hB[2*c+1]);
                ffma2(aAg, vg.x, hA[2*c]); ffma2(aAg, vg.y, hA[2*c+1]);
                ffma2(aBg, vg.x, hB[2*c]); ffma2(aBg, vg.y, hB[2*c+1]);
                ffma2(aAo, vo.x, hA[2*c]); ffma2(aAo, vo.y, hA[2*c+1]);
                ffma2(aBo, vo.x, hB[2*c]); ffma2(aBo, vo.y, hB[2*c+1]);
            }

            float lo, hi;
            upk2(lo, hi, aAi); const float vAi = lo + hi;
            upk2(lo, hi, aAf); const float vAf = lo + hi;
            upk2(lo, hi, aAg); const float vAg = lo + hi;
            upk2(lo, hi, aAo); const float vAo = lo + hi;
            upk2(lo, hi, aBi); const float vBi = lo + hi;
            upk2(lo, hi, aBf); const float vBf = lo + hi;
            upk2(lo, hi, aBg); const float vBg = lo + hi;
            upk2(lo, hi, aBo); const float vBo = lo + hi;

            const float iA = fsigm(vAi), fA = fsigm(vAf), gA = tanh_hw(vAg), oA = fsigm(vAo);
            const float iB = fsigm(vBi), fB = fsigm(vBf), gB = tanh_hw(vBg), oB = fsigm(vBo);

            float cA, cB;
            upk2(cA, cB, sC[u * BLK + tid]);
            const float cnA = fmaf(fA, cA, iA * gA);
            const float cnB = fmaf(fB, cB, iB * gB);
            sC[u * BLK + tid] = pk2(cnA, cnB);
            const float hnA = oA * tanh_hw(cnA);
            const float hnB = oB * tanh_hw(cnB);

            if (u & 1) {
                sHA[(u >> 1) * BLK + tid] = pk2(hnAp, hnA);
                sHB[(u >> 1) * BLK + tid] = pk2(hnBp, hnB);
            } else {
                hnAp = hnA; hnBp = hnB;
            }
        }

        // commit h_new -> packed h regs (same-thread slots, no sync needed)
#pragma unroll
        for (int j = 0; j < 20; j++) {
            hA[j] = sHA[j * BLK + tid];
            hB[j] = sHB[j * BLK + tid];
        }
        xA = xAn; xB = xBn;
    }

    // FC head (packed dot products)
    float lgA[C_], lgB[C_];
#pragma unroll
    for (int cc = 0; cc < C_; cc++) {
        const ulonglong2* W = (const ulonglong2*)(sWfc + cc * H_);
        ull aA = 0ULL, aB = 0ULL;
#pragma unroll
        for (int c = 0; c < 10; c++) {
            ulonglong2 w = W[c];
            ffma2(aA, w.x, hA[2*c]); ffma2(aA, w.y, hA[2*c+1]);
            ffma2(aB, w.x, hB[2*c]); ffma2(aB, w.y, hB[2*c+1]);
        }
        float lo, hi;
        upk2(lo, hi, aA); lgA[cc] = sbfc[cc] + lo + hi;
        upk2(lo, hi, aB); lgB[cc] = sbfc[cc] + lo + hi;
    }

    int bestA = 0, bestB = 0;
    float bvA = lgA[0], bvB = lgB[0];
#pragma unroll
    for (int cc = 1; cc < C_; cc++) {
        if (lgA[cc] > bvA) { bvA = lgA[cc]; bestA = cc; }
        if (lgB[cc] > bvB) { bvB = lgB[cc]; bestB = cc; }
    }

    if (logit_off >= 0) {
        *(float4*)(out + logit_off + seqA * 4) = make_float4(lgA[0], lgA[1], lgA[2], lgA[3]);
        *(float4*)(out + logit_off + seqB * 4) = make_float4(lgB[0], lgB[1], lgB[2], lgB[3]);
    }
    if (arg_off >= 0) {
        out[arg_off + seqA] = (float)bestA;
        out[arg_off + seqB] = (float)bestB;
    }
}

extern "C" void kernel_launch(void* const* d_in, const int* in_sizes, int n_in,
                              void* d_out, int out_size)
{
    const float* x    = (const float*)d_in[0];
    const float* W_ih = (const float*)d_in[1];
    const float* W_hh = (const float*)d_in[2];
    const float* b_ih = (const float*)d_in[3];
    const float* b_hh = (const float*)d_in[4];
    const float* W_fc = (const float*)d_in[5];
    const float* b_fc = (const float*)d_in[6];
    float* out = (float*)d_out;

    const long long Btot = in_sizes[0] / T_;

    long long logit_off = 0, arg_off = 4LL * Btot;   // default: both
    if (out_size == (int)(Btot * 5)) {
        logit_off = 0; arg_off = 4LL * Btot;
    } else if (out_size == (int)(Btot * 4)) {
        logit_off = 0; arg_off = -1;
    } else if (out_size == (int)Btot) {
        logit_off = -1; arg_off = 0;
    }

    cudaFuncSetAttribute(lstm_fused_kernel,
                         cudaFuncAttributeMaxDynamicSharedMemorySize,
                         (int)SMEM_BYTES);

    const int grid = (int)((Btot + SPB - 1) / SPB);
    lstm_fused_kernel<<<grid, BLK, SMEM_BYTES>>>(
        x, W_ih, W_hh, b_ih, b_hh, W_fc, b_fc, out, logit_off, arg_off);
}

// round 12
// speedup vs baseline: 1.6564x; 1.0613x over previous
#include <cuda_runtime.h>
#include <cstdint>

// Problem constants
#define T_  40
#define H_  40
#define G_  160   // 4*H
#define C_  4
#define BLK 128
#define SPB 256   // sequences per block (2 per thread)

typedef unsigned long long ull;

// HW tanh (MUFU.TANH)
__device__ __forceinline__ float tanh_hw(float x) {
    float r; asm("tanh.approx.f32 %0, %1;" : "=f"(r) : "f"(x)); return r;
}
__device__ __forceinline__ float fsigm(float x) {
    return fmaf(0.5f, tanh_hw(0.5f * x), 0.5f);
}

// packed f32x2 helpers (sm_103a core ISA — survives sm_103 ptxas)
__device__ __forceinline__ ull pk2(float lo, float hi) {
    ull r; asm("mov.b64 %0, {%1, %2};" : "=l"(r) : "f"(lo), "f"(hi)); return r;
}
__device__ __forceinline__ void upk2(float& lo, float& hi, ull v) {
    asm("mov.b64 {%0, %1}, %2;" : "=f"(lo), "=f"(hi) : "l"(v));
}
__device__ __forceinline__ void ffma2(ull& d, ull a, ull b) {
    asm("fma.rn.f32x2 %0, %1, %2, %0;" : "+l"(d) : "l"(a), "l"(b));
}

extern __shared__ float smem[];

// Shared layout (float offsets):
//   sW    [160*40] = 6400           @0
//   sWfc  [4*40]=160                @6400
//   sbfc  [8]                       @6560
//   -- 16B-aligned ull region @6568 (byte 26272) --
//   sWP  ull[160]  (w_in, 0) packed, index [u*4+gate]
//   sBP  ull[160]  (b, 0)   packed, index [u*4+gate]
//   sC   ull[40*128]  (cA,cB packed per unit per thread)
#define OFF_WFC 6400
#define OFF_BFC 6560
#define OFF_ULL 6568
#define N_C   (H_ * BLK)       // 5120 ull
#define SMEM_BYTES (OFF_ULL * 4 + (2 * G_ + N_C) * 8)   // 69792 B -> 3 CTAs/SM

__global__ __launch_bounds__(BLK, 3)
void lstm_fused_kernel(const float* __restrict__ x,
                       const float* __restrict__ W_ih,
                       const float* __restrict__ W_hh,
                       const float* __restrict__ b_ih,
                       const float* __restrict__ b_hh,
                       const float* __restrict__ W_fc,
                       const float* __restrict__ b_fc,
                       float* __restrict__ out,
                       long long logit_off,
                       long long arg_off)
{
    float* sW   = smem;
    float* sWfc = smem + OFF_WFC;
    float* sbfc = smem + OFF_BFC;
    ull*   sWP  = (ull*)(smem + OFF_ULL);
    ull*   sBP  = sWP + G_;
    ull*   sC   = sBP + G_;

    const int tid = threadIdx.x;

    // Stage weights
    for (int i = tid; i < G_ * H_; i += BLK) sW[i] = W_hh[i];
    for (int i = tid; i < G_; i += BLK) {
        const int g = i / H_, u = i % H_;
        sWP[u * 4 + g] = pk2(W_ih[i], 0.0f);
        sBP[u * 4 + g] = pk2(b_ih[i] + b_hh[i], 0.0f);
    }
    for (int i = tid; i < C_ * H_; i += BLK) sWfc[i] = W_fc[i];
    if (tid < C_) sbfc[tid] = b_fc[tid];
    for (int i = tid; i < N_C; i += BLK) sC[i] = 0ULL;
    __syncthreads();

    const long long seqA = (long long)blockIdx.x * SPB + tid;
    const long long seqB = seqA + BLK;
    const float* xA_ptr = x + seqA * T_;
    const float* xB_ptr = x + seqB * T_;

    // h pairs in registers; h_new staged via per-thread LOCAL ring (320 B,
    // default stack — keeps smem at 68 KB so 3 CTAs fit per SM)
    ull hA[20], hB[20];
    ull hLA[20], hLB[20];   // local-memory staging (dynamic index u>>1)
#pragma unroll
    for (int j = 0; j < 20; j++) { hA[j] = 0ULL; hB[j] = 0ULL; }

    float xA = xA_ptr[0];
    float xB = xB_ptr[0];
    float hnAp = 0.0f, hnBp = 0.0f;

#pragma unroll 1
    for (int t = 0; t < T_; t++) {
        float xAn = 0.0f, xBn = 0.0f;
        if (t + 1 < T_) { xAn = xA_ptr[t + 1]; xBn = xB_ptr[t + 1]; }

        const ull xx2A = pk2(xA, xA);
        const ull xx2B = pk2(xB, xB);

#pragma unroll 2
        for (int u = 0; u < H_; u++) {
            // accumulator init: (x*w_in + b, 0) via packed fma
            const ulonglong2 bp01 = *(const ulonglong2*)(sBP + u * 4);
            const ulonglong2 bp23 = *(const ulonglong2*)(sBP + u * 4 + 2);
            const ulonglong2 wp01 = *(const ulonglong2*)(sWP + u * 4);
            const ulonglong2 wp23 = *(const ulonglong2*)(sWP + u * 4 + 2);

            ull aAi = bp01.x, aAf = bp01.y, aAg = bp23.x, aAo = bp23.y;
            ull aBi = bp01.x, aBf = bp01.y, aBg = bp23.x, aBo = bp23.y;
            ffma2(aAi, wp01.x, xx2A); ffma2(aAf, wp01.y, xx2A);
            ffma2(aAg, wp23.x, xx2A); ffma2(aAo, wp23.y, xx2A);
            ffma2(aBi, wp01.x, xx2B); ffma2(aBf, wp01.y, xx2B);
            ffma2(aBg, wp23.x, xx2B); ffma2(aBo, wp23.y, xx2B);

            const ulonglong2* Wi = (const ulonglong2*)(sW + u * H_);
            const ulonglong2* Wf = (const ulonglong2*)(sW + (H_ + u) * H_);
            const ulonglong2* Wg = (const ulonglong2*)(sW + (2*H_ + u) * H_);
            const ulonglong2* Wo = (const ulonglong2*)(sW + (3*H_ + u) * H_);
#pragma unroll
            for (int c = 0; c < 10; c++) {
                ulonglong2 vi = Wi[c];
                ulonglong2 vf = Wf[c];
                ulonglong2 vg = Wg[c];
                ulonglong2 vo = Wo[c];
                ffma2(aAi, vi.x, hA[2*c]); ffma2(aAi, vi.y, hA[2*c+1]);
                ffma2(aBi, vi.x, hB[2*c]); ffma2(aBi, vi.y, hB[2*c+1]);
                ffma2(aAf, vf.x, hA[2*c]); ffma2(aAf, vf.y, hA[2*c+1]);
                ffma2(aBf, vf.x, hB[2*c]); ffma2(aBf, vf.y, hB[2*c+1]);
                ffma2(aAg, vg.x, hA[2*c]); ffma2(aAg, vg.y, hA[2*c+1]);
                ffma2(aBg, vg.x, hB[2*c]); ffma2(aBg, vg.y, hB[2*c+1]);
                ffma2(aAo, vo.x, hA[2*c]); ffma2(aAo, vo.y, hA[2*c+1]);
                ffma2(aBo, vo.x, hB[2*c]); ffma2(aBo, vo.y, hB[2*c+1]);
            }

            float lo, hi;
            upk2(lo, hi, aAi); const float vAi = lo + hi;
            upk2(lo, hi, aAf); const float vAf = lo + hi;
            upk2(lo, hi, aAg); const float vAg = lo + hi;
            upk2(lo, hi, aAo); const float vAo = lo + hi;
            upk2(lo, hi, aBi); const float vBi = lo + hi;
            upk2(lo, hi, aBf); const float vBf = lo + hi;
            upk2(lo, hi, aBg); const float vBg = lo + hi;
            upk2(lo, hi, aBo); const float vBo = lo + hi;

            const float iA = fsigm(vAi), fA = fsigm(vAf), gA = tanh_hw(vAg), oA = fsigm(vAo);
            const float iB = fsigm(vBi), fB = fsigm(vBf), gB = tanh_hw(vBg), oB = fsigm(vBo);

            float cA, cB;
            upk2(cA, cB, sC[u * BLK + tid]);
            const float cnA = fmaf(fA, cA, iA * gA);
            const float cnB = fmaf(fB, cB, iB * gB);
            sC[u * BLK + tid] = pk2(cnA, cnB);
            const float hnA = oA * tanh_hw(cnA);
            const float hnB = oB * tanh_hw(cnB);

            if (u & 1) {
                hLA[u >> 1] = pk2(hnAp, hnA);
                hLB[u >> 1] = pk2(hnBp, hnB);
            } else {
                hnAp = hnA; hnBp = hnB;
            }
        }

        // commit h_new -> packed h regs (bulk local reload, MLP=20)
#pragma unroll
        for (int j = 0; j < 20; j++) {
            hA[j] = hLA[j];
            hB[j] = hLB[j];
        }
        xA = xAn; xB = xBn;
    }

    // FC head (packed dot products)
    float lgA[C_], lgB[C_];
#pragma unroll
    for (int cc = 0; cc < C_; cc++) {
        const ulonglong2* W = (const ulonglong2*)(sWfc + cc * H_);
        ull aA = 0ULL, aB = 0ULL;
#pragma unroll
        for (int c = 0; c < 10; c++) {
            ulonglong2 w = W[c];
            ffma2(aA, w.x, hA[2*c]); ffma2(aA, w.y, hA[2*c+1]);
            ffma2(aB, w.x, hB[2*c]); ffma2(aB, w.y, hB[2*c+1]);
        }
        float lo, hi;
        upk2(lo, hi, aA); lgA[cc] = sbfc[cc] + lo + hi;
        upk2(lo, hi, aB); lgB[cc] = sbfc[cc] + lo + hi;
    }

    int bestA = 0, bestB = 0;
    float bvA = lgA[0], bvB = lgB[0];
#pragma unroll
    for (int cc = 1; cc < C_; cc++) {
        if (lgA[cc] > bvA) { bvA = lgA[cc]; bestA = cc; }
        if (lgB[cc] > bvB) { bvB = lgB[cc]; bestB = cc; }
    }

    if (logit_off >= 0) {
        *(float4*)(out + logit_off + seqA * 4) = make_float4(lgA[0], lgA[1], lgA[2], lgA[3]);
        *(float4*)(out + logit_off + seqB * 4) = make_float4(lgB[0], lgB[1], lgB[2], lgB[3]);
    }
    if (arg_off >= 0) {
        out[arg_off + seqA] = (float)bestA;
        out[arg_off + seqB] = (float)bestB;
    }
}

extern "C" void kernel_launch(void* const* d_in, const int* in_sizes, int n_in,
                              void* d_out, int out_size)
{
    const float* x    = (const float*)d_in[0];
    const float* W_ih = (const float*)d_in[1];
    const float* W_hh = (const float*)d_in[2];
    const float* b_ih = (const float*)d_in[3];
    const float* b_hh = (const float*)d_in[4];
    const float* W_fc = (const float*)d_in[5];
    const float* b_fc = (const float*)d_in[6];
    float* out = (float*)d_out;

    const long long Btot = in_sizes[0] / T_;

    long long logit_off = 0, arg_off = 4LL * Btot;   // default: both
    if (out_size == (int)(Btot * 5)) {
        logit_off = 0; arg_off = 4LL * Btot;
    } else if (out_size == (int)(Btot * 4)) {
        logit_off = 0; arg_off = -1;
    } else if (out_size == (int)Btot) {
        logit_off = -1; arg_off = 0;
    }

    cudaFuncSetAttribute(lstm_fused_kernel,
                         cudaFuncAttributeMaxDynamicSharedMemorySize,
                         (int)SMEM_BYTES);

    const int grid = (int)((Btot + SPB - 1) / SPB);
    lstm_fused_kernel<<<grid, BLK, SMEM_BYTES>>>(
        x, W_ih, W_hh, b_ih, b_hh, W_fc, b_fc, out, logit_off, arg_off);
}